// round 10
// baseline (speedup 1.0000x reference)
#include <cuda_runtime.h>
#include <cuda_fp16.h>

#define NN 50000
#define EE 800000
#define FIN 10
#define HD 64
#define NLAYERS 3
#define SCAN_BLOCKS 49

// Scratch (static device globals; no allocation allowed)
__device__ float  g_hA[NN * HD];
__device__ float  g_hB[NN * HD];
__device__ __half g_h16A[NN * HD];
__device__ __half g_h16B[NN * HD];
__device__ float  g_ews[NLAYERS * EE];     // edge weights, CSR-sorted per layer
__device__ int    g_degflag[NN + SCAN_BLOCKS + 1];  // [0..NN) deg, tail = scan flags
__device__ int    g_off[NN + 1];
__device__ int    g_cur[NN];
__device__ int    g_src[EE];               // CSR: source node per slot
__device__ int    g_scanpre[SCAN_BLOCKS + 1];

// ---- packed f32x2 helpers ----
__device__ __forceinline__ unsigned long long pk2(float x, float y) {
    unsigned long long r;
    asm("mov.b64 %0, {%1,%2};" : "=l"(r) : "f"(x), "f"(y));
    return r;
}
__device__ __forceinline__ float hsum2(unsigned long long a) {
    float x, y;
    asm("mov.b64 {%0,%1}, %2;" : "=f"(x), "=f"(y) : "l"(a));
    return x + y;
}
__device__ __forceinline__ void fma2(unsigned long long& d, unsigned long long a,
                                     unsigned long long b) {
    asm("fma.rn.f32x2 %0, %1, %2, %0;" : "+l"(d) : "l"(a), "l"(b));
}

// ---------------- proj + degree histogram (independent work overlapped) ----------------
__global__ void projhist_kernel(const float* __restrict__ x, const float* __restrict__ Wp,
                                const float* __restrict__ bp, float* __restrict__ h,
                                __half* __restrict__ h16, const int* __restrict__ ei) {
    int idx = blockIdx.x * blockDim.x + threadIdx.x;
    if (idx < EE) atomicAdd(&g_degflag[__ldg(ei + EE + idx)], 1);
    if (idx >= NN * HD) return;
    int n = idx >> 6, j = idx & 63;
    const float* xr = x + n * FIN;
    float acc = __ldg(bp + j);
#pragma unroll
    for (int k = 0; k < FIN; k++)
        acc = fmaf(__ldg(xr + k), __ldg(Wp + k * HD + j), acc);
    float r = fmaxf(acc, 0.f);
    h[idx] = r;
    h16[idx] = __float2half(r);
}

// ---------------- decoupled-lookback exclusive scan of degrees ----------------
__global__ void __launch_bounds__(1024) scan_kernel() {
    __shared__ int s[1024];
    __shared__ int s_pre;
    volatile int* flags = g_degflag + NN;
    int b = blockIdx.x, t = threadIdx.x;
    int i = b * 1024 + t;
    int v = (i < NN) ? g_degflag[i] : 0;
    s[t] = v;
    __syncthreads();
#pragma unroll
    for (int off = 1; off < 1024; off <<= 1) {
        int x = (t >= off) ? s[t - off] : 0;
        __syncthreads();
        s[t] += x;
        __syncthreads();
    }
    int agg = s[1023];
    if (t == 0) {
        int pre = 0;
        if (b > 0) {
            while (flags[b] == 0) __nanosleep(20);
            __threadfence();
            pre = g_scanpre[b];
        }
        g_scanpre[b + 1] = pre + agg;
        __threadfence();
        flags[b + 1] = 1;
        s_pre = pre;
        if (b == SCAN_BLOCKS - 1) g_off[NN] = pre + agg;
    }
    __syncthreads();
    int excl = s_pre + s[t] - v;
    if (i < NN) { g_off[i] = excl; g_cur[i] = excl; }
}

// ---------------- edge MLP + CSR fill fused ----------------
__global__ void edgefill_kernel(const int* __restrict__ ei, const float* __restrict__ ea,
                                const float* __restrict__ ew1, const float* __restrict__ eb1,
                                const float* __restrict__ ew2, const float* __restrict__ eb2) {
    __shared__ float s1[3 * 48], sb1[3 * 16], s2[3 * 16], sb2[3];
    __shared__ float sea[256 * 3];
    int t = threadIdx.x;
    if (t < 144) s1[t] = ew1[t];
    if (t < 48) { sb1[t] = eb1[t]; s2[t] = ew2[t]; }
    if (t < 3) sb2[t] = eb2[t];
    int base = blockIdx.x * 256 * 3;  // EE % 256 == 0
#pragma unroll
    for (int idx = t; idx < 768; idx += 256) sea[idx] = ea[base + idx];
    __syncthreads();
    int e = blockIdx.x * blockDim.x + t;
    int s = __ldg(ei + e);
    int d = __ldg(ei + EE + e);
    int pos = atomicAdd(&g_cur[d], 1);      // latency overlapped with MLP below
    float a0 = sea[t * 3], a1 = sea[t * 3 + 1], a2 = sea[t * 3 + 2];
    float accs[3];
#pragma unroll
    for (int l = 0; l < 3; l++) {
        const float* w1l = s1 + l * 48;
        const float* b1l = sb1 + l * 16;
        const float* w2l = s2 + l * 16;
        float acc = sb2[l];
#pragma unroll
        for (int j = 0; j < 16; j++) {
            float hj = fmaf(a2, w1l[32 + j], fmaf(a1, w1l[16 + j], fmaf(a0, w1l[j], b1l[j])));
            acc = fmaf(fmaxf(hj, 0.f), w2l[j], acc);
        }
        accs[l] = 1.f / (1.f + __expf(-acc));
    }
    g_src[pos] = s;
#pragma unroll
    for (int l = 0; l < 3; l++) g_ews[l * EE + pos] = accs[l];
}

// ---------------- fused layer: gather(fp16) + node MLP(8 nodes/warp) + LayerNorm ----------------
__global__ void __launch_bounds__(256, 3) layer_kernel(
    const float* __restrict__ h, const __half* __restrict__ h16, int layer,
    const float* __restrict__ nw, const float* __restrict__ nb,
    const float* __restrict__ lng, const float* __restrict__ lnb,
    float* __restrict__ hout, __half* __restrict__ hout16) {
    __shared__ float sW[64 * 132];          // 33.8 KB
    __shared__ float sv[8][8 * 128];        // 32 KB
    const float* __restrict__ ewl = g_ews + layer * EE;
    int tid = threadIdx.x;
    for (int idx = tid; idx < 128 * 64; idx += blockDim.x) {
        int k = idx >> 6, j = idx & 63;
        sW[j * 132 + k] = nw[idx];
    }
    __syncthreads();
    int lane = tid & 31, wrp = tid >> 5;
    int group = blockIdx.x * 8 + wrp;
    int ngroups = gridDim.x * 8;
    float nb0 = __ldg(nb + lane), nb1 = __ldg(nb + 32 + lane);
    float gg0 = __ldg(lng + lane), gg1 = __ldg(lng + 32 + lane);
    float bb0 = __ldg(lnb + lane), bb1 = __ldg(lnb + 32 + lane);
    const ulonglong2* w0p = reinterpret_cast<const ulonglong2*>(sW + lane * 132);
    const ulonglong2* w1p = reinterpret_cast<const ulonglong2*>(sW + (lane + 32) * 132);
    float* v = sv[wrp];
    for (int n0 = group * 8; n0 < NN; n0 += ngroups * 8) {
        // ---- gather 8 nodes' neighborhoods (fp16 neighbor rows, fp32 accumulate) ----
#pragma unroll 1
        for (int t = 0; t < 8; t++) {
            int n = n0 + t;
            size_t base = (size_t)n * HD;
            float2 hv = __ldg(reinterpret_cast<const float2*>(h + base) + lane);
            int beg = g_off[n], end = g_off[n + 1];
            float ax = 0.f, ay = 0.f, bx = 0.f, by = 0.f, sw = 0.f;
            int i = beg;
            while (i < end && (i & 3)) {
                int s0 = __ldg(g_src + i);
                float w0 = __ldg(ewl + i);
                float2 f0 = __half22float2(
                    __ldg(reinterpret_cast<const __half2*>(h16 + (size_t)s0 * HD) + lane));
                ax = fmaf(w0, f0.x, ax); ay = fmaf(w0, f0.y, ay);
                sw += w0;
                i++;
            }
            for (; i + 8 <= end; i += 8) {
                int4 sa = __ldg(reinterpret_cast<const int4*>(g_src + i));
                int4 sb = __ldg(reinterpret_cast<const int4*>(g_src + i + 4));
                float4 wa = __ldg(reinterpret_cast<const float4*>(ewl + i));
                float4 wb = __ldg(reinterpret_cast<const float4*>(ewl + i + 4));
                __half2 p0 = __ldg(reinterpret_cast<const __half2*>(h16 + (size_t)sa.x * HD) + lane);
                __half2 p1 = __ldg(reinterpret_cast<const __half2*>(h16 + (size_t)sa.y * HD) + lane);
                __half2 p2 = __ldg(reinterpret_cast<const __half2*>(h16 + (size_t)sa.z * HD) + lane);
                __half2 p3 = __ldg(reinterpret_cast<const __half2*>(h16 + (size_t)sa.w * HD) + lane);
                __half2 p4 = __ldg(reinterpret_cast<const __half2*>(h16 + (size_t)sb.x * HD) + lane);
                __half2 p5 = __ldg(reinterpret_cast<const __half2*>(h16 + (size_t)sb.y * HD) + lane);
                __half2 p6 = __ldg(reinterpret_cast<const __half2*>(h16 + (size_t)sb.z * HD) + lane);
                __half2 p7 = __ldg(reinterpret_cast<const __half2*>(h16 + (size_t)sb.w * HD) + lane);
                float2 f0 = __half22float2(p0), f1 = __half22float2(p1);
                float2 f2 = __half22float2(p2), f3 = __half22float2(p3);
                float2 f4 = __half22float2(p4), f5 = __half22float2(p5);
                float2 f6 = __half22float2(p6), f7 = __half22float2(p7);
                ax = fmaf(wa.x, f0.x, ax); ay = fmaf(wa.x, f0.y, ay);
                bx = fmaf(wa.y, f1.x, bx); by = fmaf(wa.y, f1.y, by);
                ax = fmaf(wa.z, f2.x, ax); ay = fmaf(wa.z, f2.y, ay);
                bx = fmaf(wa.w, f3.x, bx); by = fmaf(wa.w, f3.y, by);
                ax = fmaf(wb.x, f4.x, ax); ay = fmaf(wb.x, f4.y, ay);
                bx = fmaf(wb.y, f5.x, bx); by = fmaf(wb.y, f5.y, by);
                ax = fmaf(wb.z, f6.x, ax); ay = fmaf(wb.z, f6.y, ay);
                bx = fmaf(wb.w, f7.x, bx); by = fmaf(wb.w, f7.y, by);
                sw += ((wa.x + wa.y) + (wa.z + wa.w)) + ((wb.x + wb.y) + (wb.z + wb.w));
            }
            if (i + 4 <= end) {
                int4 sa = __ldg(reinterpret_cast<const int4*>(g_src + i));
                float4 wa = __ldg(reinterpret_cast<const float4*>(ewl + i));
                __half2 p0 = __ldg(reinterpret_cast<const __half2*>(h16 + (size_t)sa.x * HD) + lane);
                __half2 p1 = __ldg(reinterpret_cast<const __half2*>(h16 + (size_t)sa.y * HD) + lane);
                __half2 p2 = __ldg(reinterpret_cast<const __half2*>(h16 + (size_t)sa.z * HD) + lane);
                __half2 p3 = __ldg(reinterpret_cast<const __half2*>(h16 + (size_t)sa.w * HD) + lane);
                float2 f0 = __half22float2(p0), f1 = __half22float2(p1);
                float2 f2 = __half22float2(p2), f3 = __half22float2(p3);
                ax = fmaf(wa.x, f0.x, ax); ay = fmaf(wa.x, f0.y, ay);
                bx = fmaf(wa.y, f1.x, bx); by = fmaf(wa.y, f1.y, by);
                ax = fmaf(wa.z, f2.x, ax); ay = fmaf(wa.z, f2.y, ay);
                bx = fmaf(wa.w, f3.x, bx); by = fmaf(wa.w, f3.y, by);
                sw += (wa.x + wa.y) + (wa.z + wa.w);
                i += 4;
            }
            for (; i < end; i++) {
                int s0 = __ldg(g_src + i);
                float w0 = __ldg(ewl + i);
                float2 f0 = __half22float2(
                    __ldg(reinterpret_cast<const __half2*>(h16 + (size_t)s0 * HD) + lane));
                ax = fmaf(w0, f0.x, ax); ay = fmaf(w0, f0.y, ay);
                sw += w0;
            }
            float inv = 1.f / fmaxf(sw, 1e-12f);
            reinterpret_cast<float2*>(v + t * 128)[lane] = hv;
            reinterpret_cast<float2*>(v + t * 128 + 64)[lane] =
                make_float2((ax + bx) * inv, (ay + by) * inv);
        }
        __syncwarp();
        // ---- node MLP: 8 nodes share each weight load ----
        unsigned long long a0[8], a1[8];
#pragma unroll
        for (int t = 0; t < 8; t++) { a0[t] = pk2(nb0, 0.f); a1[t] = pk2(nb1, 0.f); }
#pragma unroll 4
        for (int k4 = 0; k4 < 32; k4++) {
            ulonglong2 wa = w0p[k4];
            ulonglong2 wb = w1p[k4];
#pragma unroll
            for (int t = 0; t < 8; t++) {
                ulonglong2 vv = reinterpret_cast<const ulonglong2*>(v + t * 128)[k4];
                fma2(a0[t], vv.x, wa.x); fma2(a0[t], vv.y, wa.y);
                fma2(a1[t], vv.x, wb.x); fma2(a1[t], vv.y, wb.y);
            }
        }
        // ---- residual + LayerNorm ----
#pragma unroll 1
        for (int t = 0; t < 8; t++) {
            size_t base = (size_t)(n0 + t) * HD;
            float y0 = v[t * 128 + lane] + fmaxf(hsum2(a0[t]), 0.f);
            float y1 = v[t * 128 + 32 + lane] + fmaxf(hsum2(a1[t]), 0.f);
            float s = y0 + y1;
#pragma unroll
            for (int o = 16; o > 0; o >>= 1) s += __shfl_xor_sync(0xffffffffu, s, o);
            float mu = s * 0.015625f;
            float d0 = y0 - mu, d1 = y1 - mu;
            float q = d0 * d0 + d1 * d1;
#pragma unroll
            for (int o = 16; o > 0; o >>= 1) q += __shfl_xor_sync(0xffffffffu, q, o);
            float rstd = rsqrtf(q * 0.015625f + 1e-5f);
            float o0 = fmaf(d0 * rstd, gg0, bb0);
            float o1 = fmaf(d1 * rstd, gg1, bb1);
            hout[base + lane] = o0;
            hout[base + 32 + lane] = o1;
            hout16[base + lane] = __float2half(o0);
            hout16[base + 32 + lane] = __float2half(o1);
        }
        __syncwarp();
    }
}

// ---------------- head: out = relu(h @ hw1 + hb1) @ hw2 + hb2 ----------------
__global__ void __launch_bounds__(128) head_kernel(
    const float* __restrict__ h, const float* __restrict__ hw1,
    const float* __restrict__ hb1, const float* __restrict__ hw2,
    const float* __restrict__ hb2, float* __restrict__ out) {
    __shared__ float sW[32 * 68];
    __shared__ float sv[4][4 * 64];
    int tid = threadIdx.x;
    for (int idx = tid; idx < 64 * 32; idx += blockDim.x) {
        int k = idx >> 5, j = idx & 31;
        sW[j * 68 + k] = hw1[idx];
    }
    __syncthreads();
    int lane = tid & 31, wrp = tid >> 5;
    int group = blockIdx.x * 4 + wrp;
    int ngroups = gridDim.x * 4;
    float bb1 = __ldg(hb1 + lane);
    float w2 = __ldg(hw2 + lane);
    float bb2 = __ldg(hb2);
    const ulonglong2* wp = reinterpret_cast<const ulonglong2*>(sW + lane * 68);
    float* v = sv[wrp];
    for (int n0 = group * 4; n0 < NN; n0 += ngroups * 4) {
#pragma unroll
        for (int t = 0; t < 4; t++) {
            size_t base = (size_t)(n0 + t) * HD;
            reinterpret_cast<float2*>(v + t * 64)[lane] =
                __ldg(reinterpret_cast<const float2*>(h + base) + lane);
        }
        __syncwarp();
        unsigned long long acc[4];
#pragma unroll
        for (int t = 0; t < 4; t++) acc[t] = pk2(bb1, 0.f);
#pragma unroll
        for (int k4 = 0; k4 < 16; k4++) {
            ulonglong2 w = wp[k4];
#pragma unroll
            for (int t = 0; t < 4; t++) {
                ulonglong2 vv = reinterpret_cast<const ulonglong2*>(v + t * 64)[k4];
                fma2(acc[t], vv.x, w.x); fma2(acc[t], vv.y, w.y);
            }
        }
#pragma unroll
        for (int t = 0; t < 4; t++) {
            float p = fmaxf(hsum2(acc[t]), 0.f) * w2;
#pragma unroll
            for (int o = 16; o > 0; o >>= 1) p += __shfl_xor_sync(0xffffffffu, p, o);
            if (lane == 0) out[n0 + t] = p + bb2;
        }
        __syncwarp();
    }
}

extern "C" void kernel_launch(void* const* d_in, const int* in_sizes, int n_in,
                              void* d_out, int out_size) {
    const float* x   = (const float*)d_in[0];
    const int*   ei  = (const int*)d_in[1];
    const float* ea  = (const float*)d_in[2];
    const float* Wp  = (const float*)d_in[3];
    const float* bp  = (const float*)d_in[4];
    const float* ew1 = (const float*)d_in[5];
    const float* eb1 = (const float*)d_in[6];
    const float* ew2 = (const float*)d_in[7];
    const float* eb2 = (const float*)d_in[8];
    const float* nw  = (const float*)d_in[9];
    const float* nb  = (const float*)d_in[10];
    const float* lng = (const float*)d_in[11];
    const float* lnb = (const float*)d_in[12];
    const float* hw1 = (const float*)d_in[13];
    const float* hb1 = (const float*)d_in[14];
    const float* hw2 = (const float*)d_in[15];
    const float* hb2 = (const float*)d_in[16];
    float* out = (float*)d_out;

    float* hA;  cudaGetSymbolAddress((void**)&hA, g_hA);
    float* hB;  cudaGetSymbolAddress((void**)&hB, g_hB);
    __half* h16A; cudaGetSymbolAddress((void**)&h16A, g_h16A);
    __half* h16B; cudaGetSymbolAddress((void**)&h16B, g_h16B);
    void* degp; cudaGetSymbolAddress(&degp, g_degflag);

    cudaMemsetAsync(degp, 0, (NN + SCAN_BLOCKS + 1) * sizeof(int));
    projhist_kernel<<<(NN * HD + 255) / 256, 256>>>(x, Wp, bp, hA, h16A, ei);
    scan_kernel<<<SCAN_BLOCKS, 1024>>>();
    edgefill_kernel<<<EE / 256, 256>>>(ei, ea, ew1, eb1, ew2, eb2);

    float* hin = hA;   float* hout = hB;
    __half* h16in = h16A; __half* h16out = h16B;
    for (int l = 0; l < NLAYERS; l++) {
        layer_kernel<<<782, 256>>>(hin, h16in, l, nw + l * 128 * 64, nb + l * 64,
                                   lng + l * 64, lnb + l * 64, hout, h16out);
        float* t = hin; hin = hout; hout = t;
        __half* t16 = h16in; h16in = h16out; h16out = t16;
    }
    head_kernel<<<296, 128>>>(hin, hw1, hb1, hw2, hb2, out);
}

// round 11
// speedup vs baseline: 1.0811x; 1.0811x over previous
#include <cuda_runtime.h>
#include <cuda_fp16.h>

#define NN 50000
#define EE 800000
#define FIN 10
#define HD 64
#define NLAYERS 3
#define SCAN_BLOCKS 49

// Scratch (static device globals; no allocation allowed)
__device__ float g_hA[NN * HD];
__device__ float g_hB[NN * HD];
__device__ float g_ews[NLAYERS * EE];     // edge weights, CSR-sorted per layer
__device__ int   g_degflag[NN + SCAN_BLOCKS + 1];  // [0..NN) deg, tail = scan flags
__device__ int   g_off[NN + 1];
__device__ int   g_cur[NN];
__device__ int   g_src[EE];               // CSR: source node per slot
__device__ int   g_scanpre[SCAN_BLOCKS + 1];

// ---- packed f32x2 helpers ----
__device__ __forceinline__ unsigned long long pk2(float x, float y) {
    unsigned long long r;
    asm("mov.b64 %0, {%1,%2};" : "=l"(r) : "f"(x), "f"(y));
    return r;
}
__device__ __forceinline__ float hsum2(unsigned long long a) {
    float x, y;
    asm("mov.b64 {%0,%1}, %2;" : "=f"(x), "=f"(y) : "l"(a));
    return x + y;
}
__device__ __forceinline__ void fma2(unsigned long long& d, unsigned long long a,
                                     unsigned long long b) {
    asm("fma.rn.f32x2 %0, %1, %2, %0;" : "+l"(d) : "l"(a), "l"(b));
}

// ---------------- proj + degree histogram (independent work overlapped) ----------------
__global__ void projhist_kernel(const float* __restrict__ x, const float* __restrict__ Wp,
                                const float* __restrict__ bp, float* __restrict__ h,
                                const int* __restrict__ ei) {
    int idx = blockIdx.x * blockDim.x + threadIdx.x;
    if (idx < EE) atomicAdd(&g_degflag[__ldg(ei + EE + idx)], 1);
    if (idx >= NN * HD) return;
    int n = idx >> 6, j = idx & 63;
    const float* xr = x + n * FIN;
    float acc = __ldg(bp + j);
#pragma unroll
    for (int k = 0; k < FIN; k++)
        acc = fmaf(__ldg(xr + k), __ldg(Wp + k * HD + j), acc);
    h[idx] = fmaxf(acc, 0.f);
}

// ---------------- decoupled-lookback exclusive scan of degrees ----------------
__global__ void __launch_bounds__(1024) scan_kernel() {
    __shared__ int s[1024];
    __shared__ int s_pre;
    volatile int* flags = g_degflag + NN;
    int b = blockIdx.x, t = threadIdx.x;
    int i = b * 1024 + t;
    int v = (i < NN) ? g_degflag[i] : 0;
    s[t] = v;
    __syncthreads();
#pragma unroll
    for (int off = 1; off < 1024; off <<= 1) {
        int x = (t >= off) ? s[t - off] : 0;
        __syncthreads();
        s[t] += x;
        __syncthreads();
    }
    int agg = s[1023];
    if (t == 0) {
        int pre = 0;
        if (b > 0) {
            while (flags[b] == 0) __nanosleep(20);
            __threadfence();
            pre = g_scanpre[b];
        }
        g_scanpre[b + 1] = pre + agg;
        __threadfence();
        flags[b + 1] = 1;
        s_pre = pre;
        if (b == SCAN_BLOCKS - 1) g_off[NN] = pre + agg;
    }
    __syncthreads();
    int excl = s_pre + s[t] - v;
    if (i < NN) { g_off[i] = excl; g_cur[i] = excl; }
}

// ---------------- edge MLP + CSR fill fused ----------------
__global__ void edgefill_kernel(const int* __restrict__ ei, const float* __restrict__ ea,
                                const float* __restrict__ ew1, const float* __restrict__ eb1,
                                const float* __restrict__ ew2, const float* __restrict__ eb2) {
    __shared__ float s1[3 * 48], sb1[3 * 16], s2[3 * 16], sb2[3];
    __shared__ float sea[256 * 3];
    int t = threadIdx.x;
    if (t < 144) s1[t] = ew1[t];
    if (t < 48) { sb1[t] = eb1[t]; s2[t] = ew2[t]; }
    if (t < 3) sb2[t] = eb2[t];
    int base = blockIdx.x * 256 * 3;  // EE % 256 == 0
#pragma unroll
    for (int idx = t; idx < 768; idx += 256) sea[idx] = ea[base + idx];
    __syncthreads();
    int e = blockIdx.x * blockDim.x + t;
    int s = __ldg(ei + e);
    int d = __ldg(ei + EE + e);
    int pos = atomicAdd(&g_cur[d], 1);      // latency overlapped with MLP below
    float a0 = sea[t * 3], a1 = sea[t * 3 + 1], a2 = sea[t * 3 + 2];
    float accs[3];
#pragma unroll
    for (int l = 0; l < 3; l++) {
        const float* w1l = s1 + l * 48;
        const float* b1l = sb1 + l * 16;
        const float* w2l = s2 + l * 16;
        float acc = sb2[l];
#pragma unroll
        for (int j = 0; j < 16; j++) {
            float hj = fmaf(a2, w1l[32 + j], fmaf(a1, w1l[16 + j], fmaf(a0, w1l[j], b1l[j])));
            acc = fmaf(fmaxf(hj, 0.f), w2l[j], acc);
        }
        accs[l] = 1.f / (1.f + __expf(-acc));
    }
    g_src[pos] = s;
#pragma unroll
    for (int l = 0; l < 3; l++) g_ews[l * EE + pos] = accs[l];
}

// ---------------- fused layer: gather(fp32) + node MLP(fp16 weights) + LN [+ head] -------
// 8 warps/block, 4 nodes/warp. 5 blocks/SM (regs capped at 51, smem ~42KB).
__global__ void __launch_bounds__(256, 5) layer_kernel(
    const float* __restrict__ h, int layer, const float* __restrict__ nw,
    const float* __restrict__ nb, const float* __restrict__ lng,
    const float* __restrict__ lnb, float* __restrict__ hout,
    int is_last, const float* __restrict__ hw1, const float* __restrict__ hb1,
    const float* __restrict__ hw2, const float* __restrict__ hb2,
    float* __restrict__ out) {
    __shared__ __half sW16[64 * 132];       // 16.9 KB, fp16 weight tile (transposed)
    __shared__ float sv[8][4 * 128];        // 16 KB
    __shared__ float sHW[32 * 68];          // 8.7 KB, head W1 transposed (last layer only)
    __shared__ float sH2[32];
    const float* __restrict__ ewl = g_ews + layer * EE;
    int tid = threadIdx.x;
    for (int idx = tid; idx < 128 * 64; idx += blockDim.x) {
        int k = idx >> 6, j = idx & 63;
        sW16[j * 132 + k] = __float2half(nw[idx]);
    }
    if (is_last) {
        for (int idx = tid; idx < 64 * 32; idx += blockDim.x) {
            int k = idx >> 5, j = idx & 31;
            sHW[j * 68 + k] = hw1[idx];
        }
        if (tid < 32) sH2[tid] = hw2[tid];
    }
    __syncthreads();
    int lane = tid & 31, wrp = tid >> 5;
    int group = blockIdx.x * 8 + wrp;
    int ngroups = gridDim.x * 8;
    const __half2* w0h = reinterpret_cast<const __half2*>(sW16 + lane * 132);
    const __half2* w1h = reinterpret_cast<const __half2*>(sW16 + (lane + 32) * 132);
    float* v = sv[wrp];
    for (int n0 = group * 4; n0 < NN; n0 += ngroups * 4) {
        // ---- gather 4 nodes' neighborhoods (fp32, 8 loads in flight) ----
#pragma unroll 1
        for (int t = 0; t < 4; t++) {
            int n = n0 + t;
            size_t base = (size_t)n * HD;
            float2 hv = __ldg(reinterpret_cast<const float2*>(h + base) + lane);
            int beg = g_off[n], end = g_off[n + 1];
            float ax = 0.f, ay = 0.f, bx = 0.f, by = 0.f, sw = 0.f;
            int i = beg;
            while (i < end && (i & 3)) {
                int s0 = __ldg(g_src + i);
                float w0 = __ldg(ewl + i);
                float2 h0 = __ldg(reinterpret_cast<const float2*>(h + (size_t)s0 * HD) + lane);
                ax = fmaf(w0, h0.x, ax); ay = fmaf(w0, h0.y, ay);
                sw += w0;
                i++;
            }
            for (; i + 8 <= end; i += 8) {
                int4 sa = __ldg(reinterpret_cast<const int4*>(g_src + i));
                int4 sb = __ldg(reinterpret_cast<const int4*>(g_src + i + 4));
                float4 wa = __ldg(reinterpret_cast<const float4*>(ewl + i));
                float4 wb = __ldg(reinterpret_cast<const float4*>(ewl + i + 4));
                float2 h0 = __ldg(reinterpret_cast<const float2*>(h + (size_t)sa.x * HD) + lane);
                float2 h1 = __ldg(reinterpret_cast<const float2*>(h + (size_t)sa.y * HD) + lane);
                float2 h2 = __ldg(reinterpret_cast<const float2*>(h + (size_t)sa.z * HD) + lane);
                float2 h3 = __ldg(reinterpret_cast<const float2*>(h + (size_t)sa.w * HD) + lane);
                float2 h4 = __ldg(reinterpret_cast<const float2*>(h + (size_t)sb.x * HD) + lane);
                float2 h5 = __ldg(reinterpret_cast<const float2*>(h + (size_t)sb.y * HD) + lane);
                float2 h6 = __ldg(reinterpret_cast<const float2*>(h + (size_t)sb.z * HD) + lane);
                float2 h7 = __ldg(reinterpret_cast<const float2*>(h + (size_t)sb.w * HD) + lane);
                ax = fmaf(wa.x, h0.x, ax); ay = fmaf(wa.x, h0.y, ay);
                bx = fmaf(wa.y, h1.x, bx); by = fmaf(wa.y, h1.y, by);
                ax = fmaf(wa.z, h2.x, ax); ay = fmaf(wa.z, h2.y, ay);
                bx = fmaf(wa.w, h3.x, bx); by = fmaf(wa.w, h3.y, by);
                ax = fmaf(wb.x, h4.x, ax); ay = fmaf(wb.x, h4.y, ay);
                bx = fmaf(wb.y, h5.x, bx); by = fmaf(wb.y, h5.y, by);
                ax = fmaf(wb.z, h6.x, ax); ay = fmaf(wb.z, h6.y, ay);
                bx = fmaf(wb.w, h7.x, bx); by = fmaf(wb.w, h7.y, by);
                sw += ((wa.x + wa.y) + (wa.z + wa.w)) + ((wb.x + wb.y) + (wb.z + wb.w));
            }
            if (i + 4 <= end) {
                int4 sa = __ldg(reinterpret_cast<const int4*>(g_src + i));
                float4 wa = __ldg(reinterpret_cast<const float4*>(ewl + i));
                float2 h0 = __ldg(reinterpret_cast<const float2*>(h + (size_t)sa.x * HD) + lane);
                float2 h1 = __ldg(reinterpret_cast<const float2*>(h + (size_t)sa.y * HD) + lane);
                float2 h2 = __ldg(reinterpret_cast<const float2*>(h + (size_t)sa.z * HD) + lane);
                float2 h3 = __ldg(reinterpret_cast<const float2*>(h + (size_t)sa.w * HD) + lane);
                ax = fmaf(wa.x, h0.x, ax); ay = fmaf(wa.x, h0.y, ay);
                bx = fmaf(wa.y, h1.x, bx); by = fmaf(wa.y, h1.y, by);
                ax = fmaf(wa.z, h2.x, ax); ay = fmaf(wa.z, h2.y, ay);
                bx = fmaf(wa.w, h3.x, bx); by = fmaf(wa.w, h3.y, by);
                sw += (wa.x + wa.y) + (wa.z + wa.w);
                i += 4;
            }
            for (; i < end; i++) {
                int s0 = __ldg(g_src + i);
                float w0 = __ldg(ewl + i);
                float2 h0 = __ldg(reinterpret_cast<const float2*>(h + (size_t)s0 * HD) + lane);
                ax = fmaf(w0, h0.x, ax); ay = fmaf(w0, h0.y, ay);
                sw += w0;
            }
            float inv = 1.f / fmaxf(sw, 1e-12f);
            reinterpret_cast<float2*>(v + t * 128)[lane] = hv;
            reinterpret_cast<float2*>(v + t * 128 + 64)[lane] =
                make_float2((ax + bx) * inv, (ay + by) * inv);
        }
        __syncwarp();
        // ---- node MLP: fp16 weights, fp32 f32x2 accumulate ----
        unsigned long long a0[4], a1[4];
        {
            float nb0 = __ldg(nb + lane), nb1 = __ldg(nb + 32 + lane);
#pragma unroll
            for (int t = 0; t < 4; t++) { a0[t] = pk2(nb0, 0.f); a1[t] = pk2(nb1, 0.f); }
        }
#pragma unroll 8
        for (int k4 = 0; k4 < 32; k4++) {
            __half2 wa0 = w0h[2 * k4], wa1 = w0h[2 * k4 + 1];
            __half2 wb0 = w1h[2 * k4], wb1 = w1h[2 * k4 + 1];
            float2 fa0 = __half22float2(wa0), fa1 = __half22float2(wa1);
            float2 fb0 = __half22float2(wb0), fb1 = __half22float2(wb1);
            unsigned long long ua0 = pk2(fa0.x, fa0.y), ua1 = pk2(fa1.x, fa1.y);
            unsigned long long ub0 = pk2(fb0.x, fb0.y), ub1 = pk2(fb1.x, fb1.y);
#pragma unroll
            for (int t = 0; t < 4; t++) {
                ulonglong2 vv = reinterpret_cast<const ulonglong2*>(v + t * 128)[k4];
                fma2(a0[t], vv.x, ua0); fma2(a0[t], vv.y, ua1);
                fma2(a1[t], vv.x, ub0); fma2(a1[t], vv.y, ub1);
            }
        }
        // ---- residual + LayerNorm (+ write back into v for head) ----
#pragma unroll 1
        for (int t = 0; t < 4; t++) {
            size_t base = (size_t)(n0 + t) * HD;
            float y0 = v[t * 128 + lane] + fmaxf(hsum2(a0[t]), 0.f);
            float y1 = v[t * 128 + 32 + lane] + fmaxf(hsum2(a1[t]), 0.f);
            float s = y0 + y1;
#pragma unroll
            for (int o = 16; o > 0; o >>= 1) s += __shfl_xor_sync(0xffffffffu, s, o);
            float mu = s * 0.015625f;
            float d0 = y0 - mu, d1 = y1 - mu;
            float q = d0 * d0 + d1 * d1;
#pragma unroll
            for (int o = 16; o > 0; o >>= 1) q += __shfl_xor_sync(0xffffffffu, q, o);
            float rstd = rsqrtf(q * 0.015625f + 1e-5f);
            float o0 = fmaf(d0 * rstd, __ldg(lng + lane), __ldg(lnb + lane));
            float o1 = fmaf(d1 * rstd, __ldg(lng + 32 + lane), __ldg(lnb + 32 + lane));
            if (!is_last) {
                hout[base + lane] = o0;
                hout[base + 32 + lane] = o1;
            } else {
                v[t * 128 + lane] = o0;
                v[t * 128 + 32 + lane] = o1;
            }
        }
        __syncwarp();
        // ---- fused head (last layer only): out = relu(h@hw1+hb1)@hw2+hb2 ----
        if (is_last) {
            const float4* wr = reinterpret_cast<const float4*>(sHW + lane * 68);
            float bb1 = __ldg(hb1 + lane);
#pragma unroll 1
            for (int t = 0; t < 4; t++) {
                const float4* vf = reinterpret_cast<const float4*>(v + t * 128);
                float acc = bb1;
#pragma unroll
                for (int k4 = 0; k4 < 16; k4++) {
                    float4 vv = vf[k4];
                    float4 wa = wr[k4];
                    acc = fmaf(vv.x, wa.x, fmaf(vv.y, wa.y,
                          fmaf(vv.z, wa.z, fmaf(vv.w, wa.w, acc))));
                }
                float p = fmaxf(acc, 0.f) * sH2[lane];
#pragma unroll
                for (int o = 16; o > 0; o >>= 1) p += __shfl_xor_sync(0xffffffffu, p, o);
                if (lane == 0) out[n0 + t] = p + __ldg(hb2);
            }
            __syncwarp();
        }
    }
}

extern "C" void kernel_launch(void* const* d_in, const int* in_sizes, int n_in,
                              void* d_out, int out_size) {
    const float* x   = (const float*)d_in[0];
    const int*   ei  = (const int*)d_in[1];
    const float* ea  = (const float*)d_in[2];
    const float* Wp  = (const float*)d_in[3];
    const float* bp  = (const float*)d_in[4];
    const float* ew1 = (const float*)d_in[5];
    const float* eb1 = (const float*)d_in[6];
    const float* ew2 = (const float*)d_in[7];
    const float* eb2 = (const float*)d_in[8];
    const float* nw  = (const float*)d_in[9];
    const float* nb  = (const float*)d_in[10];
    const float* lng = (const float*)d_in[11];
    const float* lnb = (const float*)d_in[12];
    const float* hw1 = (const float*)d_in[13];
    const float* hb1 = (const float*)d_in[14];
    const float* hw2 = (const float*)d_in[15];
    const float* hb2 = (const float*)d_in[16];
    float* out = (float*)d_out;

    float* hA;  cudaGetSymbolAddress((void**)&hA, g_hA);
    float* hB;  cudaGetSymbolAddress((void**)&hB, g_hB);
    void* degp; cudaGetSymbolAddress(&degp, g_degflag);

    cudaMemsetAsync(degp, 0, (NN + SCAN_BLOCKS + 1) * sizeof(int));
    projhist_kernel<<<(NN * HD + 255) / 256, 256>>>(x, Wp, bp, hA, ei);
    scan_kernel<<<SCAN_BLOCKS, 1024>>>();
    edgefill_kernel<<<EE / 256, 256>>>(ei, ea, ew1, eb1, ew2, eb2);

    float* hin = hA;
    float* hout = hB;
    for (int l = 0; l < NLAYERS; l++) {
        int is_last = (l == NLAYERS - 1);
        layer_kernel<<<740, 256>>>(hin, l, nw + l * 128 * 64, nb + l * 64,
                                   lng + l * 64, lnb + l * 64, hout,
                                   is_last, hw1, hb1, hw2, hb2, out);
        float* t = hin; hin = hout; hout = t;
    }
}

// round 12
// speedup vs baseline: 1.1660x; 1.0785x over previous
#include <cuda_runtime.h>
#include <cuda_fp16.h>

#define NN 50000
#define EE 800000
#define EEP 1000000               // padded CSR capacity (EE + up to 3 pads/node)
#define FIN 10
#define HD 64
#define NLAYERS 3
#define SCAN_BLOCKS 49

// Scratch (static device globals; no allocation allowed)
__device__ float g_hA[NN * HD];
__device__ float g_hB[NN * HD];
__device__ float g_ews[NLAYERS * EEP];    // edge weights, CSR-sorted per layer (padded)
__device__ int   g_degflag[NN + SCAN_BLOCKS + 1];  // [0..NN) deg, tail = scan flags
__device__ int   g_off[NN + 1];           // padded offsets (all multiples of 4)
__device__ int   g_cur[NN];
__device__ int   g_src[EEP];              // CSR: source node per slot (padded, pad=0)
__device__ int   g_scanpre[SCAN_BLOCKS + 1];

// ---- packed f32x2 helpers ----
__device__ __forceinline__ unsigned long long pk2(float x, float y) {
    unsigned long long r;
    asm("mov.b64 %0, {%1,%2};" : "=l"(r) : "f"(x), "f"(y));
    return r;
}
__device__ __forceinline__ float hsum2(unsigned long long a) {
    float x, y;
    asm("mov.b64 {%0,%1}, %2;" : "=f"(x), "=f"(y) : "l"(a));
    return x + y;
}
__device__ __forceinline__ void fma2(unsigned long long& d, unsigned long long a,
                                     unsigned long long b) {
    asm("fma.rn.f32x2 %0, %1, %2, %0;" : "+l"(d) : "l"(a), "l"(b));
}

// ---------------- proj + degree histogram (independent work overlapped) ----------------
__global__ void projhist_kernel(const float* __restrict__ x, const float* __restrict__ Wp,
                                const float* __restrict__ bp, float* __restrict__ h,
                                const int* __restrict__ ei) {
    int idx = blockIdx.x * blockDim.x + threadIdx.x;
    if (idx < EE) atomicAdd(&g_degflag[__ldg(ei + EE + idx)], 1);
    if (idx >= NN * HD) return;
    int n = idx >> 6, j = idx & 63;
    const float* xr = x + n * FIN;
    float acc = __ldg(bp + j);
#pragma unroll
    for (int k = 0; k < FIN; k++)
        acc = fmaf(__ldg(xr + k), __ldg(Wp + k * HD + j), acc);
    h[idx] = fmaxf(acc, 0.f);
}

// ------- decoupled-lookback exclusive scan of PADDED degrees + pad-slot zeroing -------
__global__ void __launch_bounds__(1024) scan_kernel() {
    __shared__ int s[1024];
    __shared__ int s_pre;
    volatile int* flags = g_degflag + NN;
    int b = blockIdx.x, t = threadIdx.x;
    int i = b * 1024 + t;
    int v = (i < NN) ? g_degflag[i] : 0;
    int pv = (v + 3) & ~3;                 // pad each segment to multiple of 4
    s[t] = pv;
    __syncthreads();
#pragma unroll
    for (int off = 1; off < 1024; off <<= 1) {
        int x = (t >= off) ? s[t - off] : 0;
        __syncthreads();
        s[t] += x;
        __syncthreads();
    }
    int agg = s[1023];
    if (t == 0) {
        int pre = 0;
        if (b > 0) {
            while (flags[b] == 0) __nanosleep(20);
            __threadfence();
            pre = g_scanpre[b];
        }
        g_scanpre[b + 1] = pre + agg;
        __threadfence();
        flags[b + 1] = 1;
        s_pre = pre;
        if (b == SCAN_BLOCKS - 1) g_off[NN] = pre + agg;
    }
    __syncthreads();
    int excl = s_pre + s[t] - pv;
    if (i < NN) {
        g_off[i] = excl;
        g_cur[i] = excl;
        // write pad slots: src=0, ew=0 for all 3 layers (exact no-ops in gather)
        for (int j = excl + v; j < excl + pv; j++) {
            g_src[j] = 0;
            g_ews[j] = 0.f;
            g_ews[EEP + j] = 0.f;
            g_ews[2 * EEP + j] = 0.f;
        }
    }
}

// ---------------- edge MLP + CSR fill fused ----------------
__global__ void edgefill_kernel(const int* __restrict__ ei, const float* __restrict__ ea,
                                const float* __restrict__ ew1, const float* __restrict__ eb1,
                                const float* __restrict__ ew2, const float* __restrict__ eb2) {
    __shared__ float s1[3 * 48], sb1[3 * 16], s2[3 * 16], sb2[3];
    __shared__ float sea[256 * 3];
    int t = threadIdx.x;
    if (t < 144) s1[t] = ew1[t];
    if (t < 48) { sb1[t] = eb1[t]; s2[t] = ew2[t]; }
    if (t < 3) sb2[t] = eb2[t];
    int base = blockIdx.x * 256 * 3;  // EE % 256 == 0
#pragma unroll
    for (int idx = t; idx < 768; idx += 256) sea[idx] = ea[base + idx];
    __syncthreads();
    int e = blockIdx.x * blockDim.x + t;
    int s = __ldg(ei + e);
    int d = __ldg(ei + EE + e);
    int pos = atomicAdd(&g_cur[d], 1);      // latency overlapped with MLP below
    float a0 = sea[t * 3], a1 = sea[t * 3 + 1], a2 = sea[t * 3 + 2];
    float accs[3];
#pragma unroll
    for (int l = 0; l < 3; l++) {
        const float* w1l = s1 + l * 48;
        const float* b1l = sb1 + l * 16;
        const float* w2l = s2 + l * 16;
        float acc = sb2[l];
#pragma unroll
        for (int j = 0; j < 16; j++) {
            float hj = fmaf(a2, w1l[32 + j], fmaf(a1, w1l[16 + j], fmaf(a0, w1l[j], b1l[j])));
            acc = fmaf(fmaxf(hj, 0.f), w2l[j], acc);
        }
        accs[l] = 1.f / (1.f + __expf(-acc));
    }
    g_src[pos] = s;
#pragma unroll
    for (int l = 0; l < 3; l++) g_ews[l * EEP + pos] = accs[l];
}

#define LOAD_H(s4, p0, p1, p2, p3)                                                        \
    p0 = __ldg(reinterpret_cast<const float2*>(h + (size_t)(s4).x * HD) + lane);          \
    p1 = __ldg(reinterpret_cast<const float2*>(h + (size_t)(s4).y * HD) + lane);          \
    p2 = __ldg(reinterpret_cast<const float2*>(h + (size_t)(s4).z * HD) + lane);          \
    p3 = __ldg(reinterpret_cast<const float2*>(h + (size_t)(s4).w * HD) + lane);

#define FMA_CHUNK(w4, p0, p1, p2, p3)                                                     \
    ax = fmaf((w4).x, p0.x, ax); ay = fmaf((w4).x, p0.y, ay);                             \
    bx = fmaf((w4).y, p1.x, bx); by = fmaf((w4).y, p1.y, by);                             \
    ax = fmaf((w4).z, p2.x, ax); ay = fmaf((w4).z, p2.y, ay);                             \
    bx = fmaf((w4).w, p3.x, bx); by = fmaf((w4).w, p3.y, by);                             \
    sw += ((w4).x + (w4).y) + ((w4).z + (w4).w);

// ----- fused layer: pipelined gather(fp32) + node MLP(fp16 weights) + LN [+ head] -----
// 8 warps/block, 4 nodes/warp. Gather is software-pipelined: while FMA-ing chunk c,
// chunk c+1's h-rows and chunk c+2's src/ew are in flight (padded CSR, no tail code).
__global__ void __launch_bounds__(256, 4) layer_kernel(
    const float* __restrict__ h, int layer, const float* __restrict__ nw,
    const float* __restrict__ nb, const float* __restrict__ lng,
    const float* __restrict__ lnb, float* __restrict__ hout,
    int is_last, const float* __restrict__ hw1, const float* __restrict__ hb1,
    const float* __restrict__ hw2, const float* __restrict__ hb2,
    float* __restrict__ out) {
    __shared__ __half sW16[64 * 132];       // 16.9 KB, fp16 weight tile (transposed)
    __shared__ float sv[8][4 * 128];        // 16 KB
    __shared__ float sHW[32 * 68];          // 8.7 KB, head W1 transposed (last layer only)
    __shared__ float sH2[32];
    const float* __restrict__ ewl = g_ews + layer * EEP;
    int tid = threadIdx.x;
    for (int idx = tid; idx < 128 * 64; idx += blockDim.x) {
        int k = idx >> 6, j = idx & 63;
        sW16[j * 132 + k] = __float2half(nw[idx]);
    }
    if (is_last) {
        for (int idx = tid; idx < 64 * 32; idx += blockDim.x) {
            int k = idx >> 5, j = idx & 31;
            sHW[j * 68 + k] = hw1[idx];
        }
        if (tid < 32) sH2[tid] = hw2[tid];
    }
    __syncthreads();
    int lane = tid & 31, wrp = tid >> 5;
    int group = blockIdx.x * 8 + wrp;
    int ngroups = gridDim.x * 8;
    const __half2* w0h = reinterpret_cast<const __half2*>(sW16 + lane * 132);
    const __half2* w1h = reinterpret_cast<const __half2*>(sW16 + (lane + 32) * 132);
    float* v = sv[wrp];
    for (int n0 = group * 4; n0 < NN; n0 += ngroups * 4) {
        // ---- gather 4 nodes' neighborhoods (software-pipelined) ----
#pragma unroll 1
        for (int t = 0; t < 4; t++) {
            int n = n0 + t;
            size_t base = (size_t)n * HD;
            float2 hv = __ldg(reinterpret_cast<const float2*>(h + base) + lane);
            int beg = g_off[n], end = g_off[n + 1];
            float ax = 0.f, ay = 0.f, bx = 0.f, by = 0.f, sw = 0.f;
            int nch = (end - beg) >> 2;     // segments are 4-aligned and 4-padded
            if (nch > 0) {
                int4 sA = __ldg(reinterpret_cast<const int4*>(g_src + beg));
                float4 wA = __ldg(reinterpret_cast<const float4*>(ewl + beg));
                int4 sB;
                float4 wB;
                if (nch > 1) {
                    sB = __ldg(reinterpret_cast<const int4*>(g_src + beg + 4));
                    wB = __ldg(reinterpret_cast<const float4*>(ewl + beg + 4));
                }
                float2 hA0, hA1, hA2, hA3;
                LOAD_H(sA, hA0, hA1, hA2, hA3);
                int i = beg + 8;
#pragma unroll 2
                for (int c = 0; c + 2 < nch; c++, i += 4) {
                    int4 sC = __ldg(reinterpret_cast<const int4*>(g_src + i));
                    float4 wC = __ldg(reinterpret_cast<const float4*>(ewl + i));
                    float2 hB0, hB1, hB2, hB3;
                    LOAD_H(sB, hB0, hB1, hB2, hB3);
                    FMA_CHUNK(wA, hA0, hA1, hA2, hA3);
                    wA = wB; hA0 = hB0; hA1 = hB1; hA2 = hB2; hA3 = hB3;
                    sB = sC; wB = wC;
                }
                if (nch > 1) {
                    float2 hB0, hB1, hB2, hB3;
                    LOAD_H(sB, hB0, hB1, hB2, hB3);
                    FMA_CHUNK(wA, hA0, hA1, hA2, hA3);
                    FMA_CHUNK(wB, hB0, hB1, hB2, hB3);
                } else {
                    FMA_CHUNK(wA, hA0, hA1, hA2, hA3);
                }
            }
            float inv = 1.f / fmaxf(sw, 1e-12f);
            reinterpret_cast<float2*>(v + t * 128)[lane] = hv;
            reinterpret_cast<float2*>(v + t * 128 + 64)[lane] =
                make_float2((ax + bx) * inv, (ay + by) * inv);
        }
        __syncwarp();
        // ---- node MLP: fp16 weights, fp32 f32x2 accumulate ----
        unsigned long long a0[4], a1[4];
        {
            float nb0 = __ldg(nb + lane), nb1 = __ldg(nb + 32 + lane);
#pragma unroll
            for (int t = 0; t < 4; t++) { a0[t] = pk2(nb0, 0.f); a1[t] = pk2(nb1, 0.f); }
        }
#pragma unroll 8
        for (int k4 = 0; k4 < 32; k4++) {
            __half2 wa0 = w0h[2 * k4], wa1 = w0h[2 * k4 + 1];
            __half2 wb0 = w1h[2 * k4], wb1 = w1h[2 * k4 + 1];
            float2 fa0 = __half22float2(wa0), fa1 = __half22float2(wa1);
            float2 fb0 = __half22float2(wb0), fb1 = __half22float2(wb1);
            unsigned long long ua0 = pk2(fa0.x, fa0.y), ua1 = pk2(fa1.x, fa1.y);
            unsigned long long ub0 = pk2(fb0.x, fb0.y), ub1 = pk2(fb1.x, fb1.y);
#pragma unroll
            for (int t = 0; t < 4; t++) {
                ulonglong2 vv = reinterpret_cast<const ulonglong2*>(v + t * 128)[k4];
                fma2(a0[t], vv.x, ua0); fma2(a0[t], vv.y, ua1);
                fma2(a1[t], vv.x, ub0); fma2(a1[t], vv.y, ub1);
            }
        }
        // ---- residual + LayerNorm (+ write back into v for head) ----
#pragma unroll 1
        for (int t = 0; t < 4; t++) {
            size_t base = (size_t)(n0 + t) * HD;
            float y0 = v[t * 128 + lane] + fmaxf(hsum2(a0[t]), 0.f);
            float y1 = v[t * 128 + 32 + lane] + fmaxf(hsum2(a1[t]), 0.f);
            float s = y0 + y1;
#pragma unroll
            for (int o = 16; o > 0; o >>= 1) s += __shfl_xor_sync(0xffffffffu, s, o);
            float mu = s * 0.015625f;
            float d0 = y0 - mu, d1 = y1 - mu;
            float q = d0 * d0 + d1 * d1;
#pragma unroll
            for (int o = 16; o > 0; o >>= 1) q += __shfl_xor_sync(0xffffffffu, q, o);
            float rstd = rsqrtf(q * 0.015625f + 1e-5f);
            float o0 = fmaf(d0 * rstd, __ldg(lng + lane), __ldg(lnb + lane));
            float o1 = fmaf(d1 * rstd, __ldg(lng + 32 + lane), __ldg(lnb + 32 + lane));
            if (!is_last) {
                hout[base + lane] = o0;
                hout[base + 32 + lane] = o1;
            } else {
                v[t * 128 + lane] = o0;
                v[t * 128 + 32 + lane] = o1;
            }
        }
        __syncwarp();
        // ---- fused head (last layer only): out = relu(h@hw1+hb1)@hw2+hb2 ----
        if (is_last) {
            const float4* wr = reinterpret_cast<const float4*>(sHW + lane * 68);
            float bb1 = __ldg(hb1 + lane);
#pragma unroll 1
            for (int t = 0; t < 4; t++) {
                const float4* vf = reinterpret_cast<const float4*>(v + t * 128);
                float acc = bb1;
#pragma unroll
                for (int k4 = 0; k4 < 16; k4++) {
                    float4 vv = vf[k4];
                    float4 wa = wr[k4];
                    acc = fmaf(vv.x, wa.x, fmaf(vv.y, wa.y,
                          fmaf(vv.z, wa.z, fmaf(vv.w, wa.w, acc))));
                }
                float p = fmaxf(acc, 0.f) * sH2[lane];
#pragma unroll
                for (int o = 16; o > 0; o >>= 1) p += __shfl_xor_sync(0xffffffffu, p, o);
                if (lane == 0) out[n0 + t] = p + __ldg(hb2);
            }
            __syncwarp();
        }
    }
}

extern "C" void kernel_launch(void* const* d_in, const int* in_sizes, int n_in,
                              void* d_out, int out_size) {
    const float* x   = (const float*)d_in[0];
    const int*   ei  = (const int*)d_in[1];
    const float* ea  = (const float*)d_in[2];
    const float* Wp  = (const float*)d_in[3];
    const float* bp  = (const float*)d_in[4];
    const float* ew1 = (const float*)d_in[5];
    const float* eb1 = (const float*)d_in[6];
    const float* ew2 = (const float*)d_in[7];
    const float* eb2 = (const float*)d_in[8];
    const float* nw  = (const float*)d_in[9];
    const float* nb  = (const float*)d_in[10];
    const float* lng = (const float*)d_in[11];
    const float* lnb = (const float*)d_in[12];
    const float* hw1 = (const float*)d_in[13];
    const float* hb1 = (const float*)d_in[14];
    const float* hw2 = (const float*)d_in[15];
    const float* hb2 = (const float*)d_in[16];
    float* out = (float*)d_out;

    float* hA;  cudaGetSymbolAddress((void**)&hA, g_hA);
    float* hB;  cudaGetSymbolAddress((void**)&hB, g_hB);
    void* degp; cudaGetSymbolAddress(&degp, g_degflag);

    cudaMemsetAsync(degp, 0, (NN + SCAN_BLOCKS + 1) * sizeof(int));
    projhist_kernel<<<(NN * HD + 255) / 256, 256>>>(x, Wp, bp, hA, ei);
    scan_kernel<<<SCAN_BLOCKS, 1024>>>();
    edgefill_kernel<<<EE / 256, 256>>>(ei, ea, ew1, eb1, ew2, eb2);

    float* hin = hA;
    float* hout = hB;
    for (int l = 0; l < NLAYERS; l++) {
        int is_last = (l == NLAYERS - 1);
        layer_kernel<<<592, 256>>>(hin, l, nw + l * 128 * 64, nb + l * 64,
                                   lng + l * 64, lnb + l * 64, hout,
                                   is_last, hw1, hb1, hw2, hb2, out);
        float* t = hin; hin = hout; hout = t;
    }
}